// round 1
// baseline (speedup 1.0000x reference)
#include <cuda_runtime.h>
#include <cuda_fp16.h>
#include <cstdint>
#include <cstddef>

// Problem shape (fixed by setup_inputs)
#define M_DIM 2048
#define K_DIM 4096
#define N_DIM 11008
#define GS    128
#define NPACK (N_DIM / 8)   // 1376

// Scratch: dequantized W (fp16, [K, N]) and converted x (fp16, [M, K])
__device__ __half g_wh[(size_t)K_DIM * N_DIM];
__device__ __half g_xh[(size_t)M_DIM * K_DIM];

// ---------------------------------------------------------------------------
// Kernel 1: AWQ int4 dequant -> fp16 W[K][N]
// nibble for logical position m is at shift INV[m]*4, INV = {0,4,1,5,2,6,3,7}
// ---------------------------------------------------------------------------
__device__ __forceinline__ uint32_t pack_h2(float a, float b) {
    __half2 h = __floats2half2_rn(a, b);
    return *reinterpret_cast<uint32_t*>(&h);
}

__global__ void dequant_kernel(const int* __restrict__ qw,
                               const int* __restrict__ qz,
                               const float* __restrict__ sc) {
    int idx = blockIdx.x * blockDim.x + threadIdx.x;
    if (idx >= K_DIM * NPACK) return;
    int k = idx / NPACK;
    int c = idx % NPACK;
    int g = k / GS;

    uint32_t w = (uint32_t)qw[idx];
    uint32_t z = (uint32_t)qz[g * NPACK + c];
    const float* s = sc + (size_t)g * N_DIM + c * 8;

    float v[8];
#pragma unroll
    for (int m = 0; m < 8; m++) {
        const int sh[8] = {0, 16, 4, 20, 8, 24, 12, 28};
        int qv = (int)((w >> sh[m]) & 0xF);
        int zv = (int)((z >> sh[m]) & 0xF);
        v[m] = (float)(qv - zv) * s[m];
    }
    uint4 out;
    out.x = pack_h2(v[0], v[1]);
    out.y = pack_h2(v[2], v[3]);
    out.z = pack_h2(v[4], v[5]);
    out.w = pack_h2(v[6], v[7]);
    *reinterpret_cast<uint4*>(&g_wh[(size_t)k * N_DIM + c * 8]) = out;
}

// ---------------------------------------------------------------------------
// Kernel 2: x fp32 -> fp16
// ---------------------------------------------------------------------------
__global__ void xconv_kernel(const float* __restrict__ x) {
    int idx = blockIdx.x * blockDim.x + threadIdx.x;
    if (idx >= (M_DIM * K_DIM) / 8) return;
    const float4* xf = reinterpret_cast<const float4*>(x);
    float4 a = xf[2 * idx];
    float4 b = xf[2 * idx + 1];
    uint4 out;
    out.x = pack_h2(a.x, a.y);
    out.y = pack_h2(a.z, a.w);
    out.z = pack_h2(b.x, b.y);
    out.w = pack_h2(b.z, b.w);
    *reinterpret_cast<uint4*>(&g_xh[(size_t)idx * 8]) = out;
}

// ---------------------------------------------------------------------------
// Kernel 3: fp16 GEMM, fp32 accumulate. C[M,N] = Xh[M,K] * Wh[K,N]
// BM=128, BN=128, BK=32; 8 warps (2 x 4), warp tile 64x32, m16n8k16 mma.sync.
// Double-buffered cp.async.
// ---------------------------------------------------------------------------
#define BM 128
#define BN 128
#define BK 32
#define LDA 40    // halfs; 80B row stride -> conflict-free ldmatrix phases
#define LDB 136   // halfs; 272B row stride -> conflict-free ldmatrix phases

__device__ __forceinline__ uint32_t smem_u32(const void* p) {
    return (uint32_t)__cvta_generic_to_shared(p);
}

__global__ __launch_bounds__(256, 2)
void gemm_f16_kernel(float* __restrict__ C) {
    __shared__ __half As[2][BM * LDA];
    __shared__ __half Bs[2][BK * LDB];

    const int tid  = threadIdx.x;
    const int warp = tid >> 5;
    const int lane = tid & 31;
    const int wm   = warp >> 2;   // 0..1
    const int wn   = warp & 3;    // 0..3
    const int bm   = blockIdx.y * BM;
    const int bn   = blockIdx.x * BN;

    float acc[4][4][4];
#pragma unroll
    for (int i = 0; i < 4; i++)
#pragma unroll
        for (int j = 0; j < 4; j++)
#pragma unroll
            for (int r = 0; r < 4; r++) acc[i][j][r] = 0.f;

    // global->smem tile copy indices (16B chunks)
    const int arow = tid >> 2, acol = (tid & 3) * 8;   // A: 128 rows x 4 chunks
    const int brow = tid >> 4, bcol = (tid & 15) * 8;  // B: 32 rows x 16 chunks

    const __half* gA = g_xh + (size_t)bm * K_DIM;
    const __half* gB = g_wh + bn;

    auto load_stage = [&](int st, int k0) {
#pragma unroll
        for (int i = 0; i < 2; i++) {
            int r = arow + i * 64;
            uint32_t d = smem_u32(&As[st][r * LDA + acol]);
            const __half* s = gA + (size_t)r * K_DIM + k0 + acol;
            asm volatile("cp.async.cg.shared.global [%0], [%1], 16;\n" ::"r"(d), "l"(s));
        }
#pragma unroll
        for (int i = 0; i < 2; i++) {
            int r = brow + i * 16;
            uint32_t d = smem_u32(&Bs[st][r * LDB + bcol]);
            const __half* s = gB + (size_t)(k0 + r) * N_DIM + bcol;
            asm volatile("cp.async.cg.shared.global [%0], [%1], 16;\n" ::"r"(d), "l"(s));
        }
        asm volatile("cp.async.commit_group;\n");
    };

    load_stage(0, 0);

    const int NK = K_DIM / BK;
    for (int kt = 0; kt < NK; kt++) {
        const int st = kt & 1;
        if (kt + 1 < NK) {
            load_stage(st ^ 1, (kt + 1) * BK);
            asm volatile("cp.async.wait_group 1;\n");
        } else {
            asm volatile("cp.async.wait_group 0;\n");
        }
        __syncthreads();

#pragma unroll
        for (int kp = 0; kp < 2; kp++) {
            uint32_t a[4][4];
            uint32_t b[4][2];
#pragma unroll
            for (int mi = 0; mi < 4; mi++) {
                int row = wm * 64 + mi * 16 + (lane & 15);
                int col = kp * 16 + (lane >> 4) * 8;
                uint32_t addr = smem_u32(&As[st][row * LDA + col]);
                asm volatile(
                    "ldmatrix.sync.aligned.x4.m8n8.shared.b16 {%0,%1,%2,%3}, [%4];"
                    : "=r"(a[mi][0]), "=r"(a[mi][1]), "=r"(a[mi][2]), "=r"(a[mi][3])
                    : "r"(addr));
            }
#pragma unroll
            for (int ni = 0; ni < 4; ni++) {
                int row = kp * 16 + (lane & 15);
                int col = wn * 32 + ni * 8;
                uint32_t addr = smem_u32(&Bs[st][row * LDB + col]);
                asm volatile(
                    "ldmatrix.sync.aligned.x2.trans.m8n8.shared.b16 {%0,%1}, [%2];"
                    : "=r"(b[ni][0]), "=r"(b[ni][1])
                    : "r"(addr));
            }
#pragma unroll
            for (int mi = 0; mi < 4; mi++)
#pragma unroll
                for (int ni = 0; ni < 4; ni++) {
                    asm volatile(
                        "mma.sync.aligned.m16n8k16.row.col.f32.f16.f16.f32 "
                        "{%0,%1,%2,%3}, {%4,%5,%6,%7}, {%8,%9}, {%0,%1,%2,%3};"
                        : "+f"(acc[mi][ni][0]), "+f"(acc[mi][ni][1]),
                          "+f"(acc[mi][ni][2]), "+f"(acc[mi][ni][3])
                        : "r"(a[mi][0]), "r"(a[mi][1]), "r"(a[mi][2]), "r"(a[mi][3]),
                          "r"(b[ni][0]), "r"(b[ni][1]));
                }
        }
        __syncthreads();
    }

    // epilogue: fp32 C
#pragma unroll
    for (int mi = 0; mi < 4; mi++) {
        int row = bm + wm * 64 + mi * 16 + (lane >> 2);
#pragma unroll
        for (int ni = 0; ni < 4; ni++) {
            int col = bn + wn * 32 + ni * 8 + (lane & 3) * 2;
            float2* p0 = reinterpret_cast<float2*>(&C[(size_t)row * N_DIM + col]);
            float2* p1 = reinterpret_cast<float2*>(&C[(size_t)(row + 8) * N_DIM + col]);
            *p0 = make_float2(acc[mi][ni][0], acc[mi][ni][1]);
            *p1 = make_float2(acc[mi][ni][2], acc[mi][ni][3]);
        }
    }
}

// ---------------------------------------------------------------------------
// Launch: inputs (metadata order): x, qweight, qzeros, scales, group_size
// ---------------------------------------------------------------------------
extern "C" void kernel_launch(void* const* d_in, const int* in_sizes, int n_in,
                              void* d_out, int out_size) {
    const float* x   = (const float*)d_in[0];
    const int*   qw  = (const int*)d_in[1];
    const int*   qz  = (const int*)d_in[2];
    const float* sc  = (const float*)d_in[3];
    float*       out = (float*)d_out;

    {
        int total = K_DIM * NPACK;
        dequant_kernel<<<(total + 255) / 256, 256>>>(qw, qz, sc);
    }
    {
        int total = (M_DIM * K_DIM) / 8;
        xconv_kernel<<<(total + 255) / 256, 256>>>(x);
    }
    {
        dim3 grid(N_DIM / BN, M_DIM / BM);  // 86 x 16
        gemm_f16_kernel<<<grid, 256>>>(out);
    }
}